// round 1
// baseline (speedup 1.0000x reference)
#include <cuda_runtime.h>
#include <math.h>

// ---------------------------------------------------------------------------
// GraphUnet: N=4096, DIM=320, L=2, KS=(0.8,0.6) -> kk0=3276, kk1=1965
// ---------------------------------------------------------------------------
#define N0   4096
#define DD   320
#define DD2  640
#define KK0  3276
#define KK1  1965
#define NW   128          // bitmask words per row (4096/32)

// ---------------- static scratch (no allocations allowed) ------------------
__device__ float    g_X0 [N0*DD];
__device__ float    g_X1d[N0*DD];
__device__ float    g_X2d[N0*DD];
__device__ float    g_Xb [N0*DD];
__device__ float    g_X1 [N0*DD];
__device__ float    g_X2 [N0*DD];
__device__ float    g_G  [N0*DD];
__device__ float    g_Xu1[N0*DD];
__device__ float    g_Xu0[N0*DD];
__device__ float    g_cat[N0*DD2];
__device__ unsigned g_bm [N0*NW];
__device__ float    g_h1 [N0];
__device__ float    g_e  [N0];
__device__ float    g_eh [N0];
__device__ float    g_sc [N0];
__device__ float    g_vals0[N0];
__device__ float    g_vals1[N0];
__device__ int      g_idx0[N0];
__device__ int      g_idx1[N0];
__device__ float    g_catW[2*DD2*DD];
__device__ float    g_biasGS[2*DD];

// ---------------------------------------------------------------------------
// Bitmask build: one thread per A entry, ballot per 32 columns.
// ---------------------------------------------------------------------------
__global__ void build_mask_kernel(const float* __restrict__ A, unsigned* __restrict__ bm) {
    int gid = blockIdx.x * blockDim.x + threadIdx.x;      // 0 .. 4096*4096-1
    float v = A[gid];
    unsigned b = __ballot_sync(0xffffffffu, v != 0.0f);
    if ((threadIdx.x & 31) == 0) bm[gid >> 5] = b;
}

// ---------------------------------------------------------------------------
// Generic fp32 GEMM: C[M,N] = act(A[M,K] @ B[K,N] + bias[N]) (+ res[M,N])
// BM=BN=64, BK=16, 256 threads, 4x4 microtile. N multiple of 64, K mult of 16.
// act: 0=none 1=relu 2=sigmoid. res added AFTER activation.
// ---------------------------------------------------------------------------
#define TBM 64
#define TBN 64
#define TBK 16

__global__ __launch_bounds__(256) void gemm_kernel(
    int M, int N, int K,
    const float* __restrict__ A, int lda,
    const float* __restrict__ B, int ldb,
    const float* __restrict__ bias,
    float* __restrict__ C, int ldc,
    const float* __restrict__ res, int ldres,
    int act)
{
    __shared__ float As[TBK][TBM];
    __shared__ float Bs[TBK][TBN];

    int tid = threadIdx.x;
    int tx = tid & 15;
    int ty = tid >> 4;
    int row0 = blockIdx.y * TBM;
    int col0 = blockIdx.x * TBN;

    // A tile load map: float4 per thread
    int am = tid >> 2;
    int ak = (tid & 3) * 4;
    // B tile load map
    int bk = tid >> 4;
    int bn = (tid & 15) * 4;

    float acc[4][4] = {};

    for (int k0 = 0; k0 < K; k0 += TBK) {
        int gm = row0 + am;
        float4 av = make_float4(0.f, 0.f, 0.f, 0.f);
        if (gm < M)
            av = *reinterpret_cast<const float4*>(A + (size_t)gm * lda + k0 + ak);
        As[ak + 0][am] = av.x;
        As[ak + 1][am] = av.y;
        As[ak + 2][am] = av.z;
        As[ak + 3][am] = av.w;

        float4 bv = *reinterpret_cast<const float4*>(B + (size_t)(k0 + bk) * ldb + col0 + bn);
        *reinterpret_cast<float4*>(&Bs[bk][bn]) = bv;

        __syncthreads();

#pragma unroll
        for (int kk = 0; kk < TBK; kk++) {
            float4 a = *reinterpret_cast<const float4*>(&As[kk][ty * 4]);
            float4 b = *reinterpret_cast<const float4*>(&Bs[kk][tx * 4]);
            acc[0][0] += a.x * b.x; acc[0][1] += a.x * b.y; acc[0][2] += a.x * b.z; acc[0][3] += a.x * b.w;
            acc[1][0] += a.y * b.x; acc[1][1] += a.y * b.y; acc[1][2] += a.y * b.z; acc[1][3] += a.y * b.w;
            acc[2][0] += a.z * b.x; acc[2][1] += a.z * b.y; acc[2][2] += a.z * b.z; acc[2][3] += a.z * b.w;
            acc[3][0] += a.w * b.x; acc[3][1] += a.w * b.y; acc[3][2] += a.w * b.z; acc[3][3] += a.w * b.w;
        }
        __syncthreads();
    }

    int rbase = row0 + ty * 4;
    int cbase = col0 + tx * 4;
#pragma unroll
    for (int mi = 0; mi < 4; mi++) {
        int r = rbase + mi;
        if (r >= M) continue;
#pragma unroll
        for (int ni = 0; ni < 4; ni++) {
            int c = cbase + ni;
            float v = acc[mi][ni] + bias[c];
            if (act == 1)      v = fmaxf(v, 0.f);
            else if (act == 2) v = 1.f / (1.f + expf(-v));
            if (res) v += res[(size_t)r * ldres + c];
            C[(size_t)r * ldc + c] = v;
        }
    }
}

// ---------------------------------------------------------------------------
// GEMV: h1[r] = X[r,:] @ w + (*pwb + *pb). One warp per row.
// ---------------------------------------------------------------------------
__global__ void gemv_kernel(int M, const float* __restrict__ X,
                            const float* __restrict__ w,
                            const float* __restrict__ pwb,
                            const float* __restrict__ pb,
                            float* __restrict__ h1)
{
    int warp = (blockIdx.x * blockDim.x + threadIdx.x) >> 5;
    int lane = threadIdx.x & 31;
    if (warp >= M) return;
    const float* xr = X + (size_t)warp * DD;
    float s = 0.f;
    for (int k = lane; k < DD; k += 32) s += xr[k] * w[k];
#pragma unroll
    for (int o = 16; o > 0; o >>= 1) s += __shfl_down_sync(0xffffffffu, s, o);
    if (lane == 0) h1[warp] = s + pwb[0] + pb[0];
}

// e[i] = exp(phi0*h1[i]); eh[i] = e[i]*h1[i]
__global__ void compute_e_kernel(int n, const float* __restrict__ h1,
                                 const float* __restrict__ phi0,
                                 float* __restrict__ e, float* __restrict__ eh)
{
    int i = blockIdx.x * blockDim.x + threadIdx.x;
    if (i >= n) return;
    float ex = expf(phi0[0] * h1[i]);
    e[i] = ex;
    eh[i] = ex * h1[i];
}

// Level-0 aggregation: block per row, 128 threads (1 word each).
__global__ void agg0_kernel(const unsigned* __restrict__ bm,
                            const float* __restrict__ e,
                            const float* __restrict__ eh,
                            float* __restrict__ scores)
{
    int r = blockIdx.x;
    int t = threadIdx.x;          // 0..127
    unsigned w = bm[r * NW + t];
    if ((r >> 5) == t) w |= (1u << (r & 31));   // self (A + I)
    float se = 0.f, sh = 0.f;
    while (w) {
        int b = __ffs(w) - 1;
        w &= w - 1;
        int j = t * 32 + b;
        se += e[j];
        sh += eh[j];
    }
    __shared__ float s1[128], s2[128];
    s1[t] = se; s2[t] = sh;
    __syncthreads();
    for (int o = 64; o > 0; o >>= 1) {
        if (t < o) { s1[t] += s1[t + o]; s2[t] += s2[t + o]; }
        __syncthreads();
    }
    if (t == 0) {
        float agg = (s2[0] / s1[0]) * 0.01f;
        scores[r] = 1.f / (1.f + expf(-agg));
    }
}

// Level-1 aggregation over A[idx0][:,idx0] via gathered bit tests.
__global__ void agg1_kernel(const unsigned* __restrict__ bm,
                            const int* __restrict__ idx0, int n1,
                            const float* __restrict__ e,
                            const float* __restrict__ eh,
                            float* __restrict__ scores)
{
    __shared__ unsigned row[NW];
    int r = blockIdx.x;
    int t = threadIdx.x;          // 256 threads
    int orig = idx0[r];
    if (t < NW) row[t] = bm[orig * NW + t];
    __syncthreads();
    float se = 0.f, sh = 0.f;
    for (int j = t; j < n1; j += 256) {
        int c = idx0[j];
        bool in = (row[c >> 5] >> (c & 31)) & 1u;
        if (j == r) in = true;
        if (in) { se += e[j]; sh += eh[j]; }
    }
    __shared__ float s1[256], s2[256];
    s1[t] = se; s2[t] = sh;
    __syncthreads();
    for (int o = 128; o > 0; o >>= 1) {
        if (t < o) { s1[t] += s1[t + o]; s2[t] += s2[t + o]; }
        __syncthreads();
    }
    if (t == 0) {
        float agg = (s2[0] / s1[0]) * 0.01f;
        scores[r] = 1.f / (1.f + expf(-agg));
    }
}

// Stable top-k by full rank: rank = #{s_j > s_i} + #{j<i: s_j == s_i}
// Exactly replicates jax.lax.top_k order (desc, ties -> lower index first).
__global__ void rank_select_kernel(const float* __restrict__ s, int n, int kk,
                                   int* __restrict__ idx, float* __restrict__ vals)
{
    __shared__ float sh[256];
    int i = blockIdx.x * blockDim.x + threadIdx.x;
    float si = (i < n) ? s[i] : 0.f;
    int rank = 0;
    for (int base = 0; base < n; base += 256) {
        int j = base + threadIdx.x;
        sh[threadIdx.x] = (j < n) ? s[j] : -3.0e38f;
        __syncthreads();
        int lim = min(256, n - base);
        for (int t = 0; t < lim; t++) {
            float sj = sh[t];
            int j2 = base + t;
            if (sj > si || (sj == si && j2 < i)) rank++;
        }
        __syncthreads();
    }
    if (i < n && rank < kk) { idx[rank] = i; vals[rank] = si; }
}

// dst[r,:] = src[idx[r],:] * vals[r]
__global__ void gather_scale_kernel(const float* __restrict__ src,
                                    const int* __restrict__ idx,
                                    const float* __restrict__ vals,
                                    int rows, float* __restrict__ dst)
{
    int gid = blockIdx.x * blockDim.x + threadIdx.x;
    if (gid >= rows * DD) return;
    int r = gid / DD, c = gid % DD;
    dst[gid] = src[(size_t)idx[r] * DD + c] * vals[r];
}

__global__ void zero_kernel(float* __restrict__ p, int n) {
    int gid = blockIdx.x * blockDim.x + threadIdx.x;
    if (gid < n) p[gid] = 0.f;
}

// dst[idx[r]*ldd + c] = src[r*DD + c]
__global__ void scatter_kernel(float* __restrict__ dst, int ldd,
                               const int* __restrict__ idx,
                               const float* __restrict__ src, int rows)
{
    int gid = blockIdx.x * blockDim.x + threadIdx.x;
    if (gid >= rows * DD) return;
    int r = gid / DD, c = gid % DD;
    dst[(size_t)idx[r] * ldd + c] = src[gid];
}

// dst[r*ldd + c] = src[r*lds + c], cols = DD
__global__ void copy_block_kernel(float* __restrict__ dst, int ldd,
                                  const float* __restrict__ src, int lds, int rows)
{
    int gid = blockIdx.x * blockDim.x + threadIdx.x;
    if (gid >= rows * DD) return;
    int r = gid / DD, c = gid % DD;
    dst[(size_t)r * ldd + c] = src[(size_t)r * lds + c];
}

// biasGS = ag_bg + ag_bs (both (L,DD) flat, 640 entries)
__global__ void add_bias_kernel(const float* __restrict__ a,
                                const float* __restrict__ b,
                                float* __restrict__ o, int n)
{
    int gid = blockIdx.x * blockDim.x + threadIdx.x;
    if (gid < n) o[gid] = a[gid] + b[gid];
}

// ---------------------------------------------------------------------------
extern "C" void kernel_launch(void* const* d_in, const int* in_sizes, int n_in,
                              void* d_out, int out_size)
{
    const float* A     = (const float*)d_in[0];
    const float* Xin   = (const float*)d_in[1];
    const float* W0    = (const float*)d_in[2];
    const float* b0    = (const float*)d_in[3];
    const float* Wb    = (const float*)d_in[4];
    const float* bb    = (const float*)d_in[5];
    const float* We    = (const float*)d_in[6];
    const float* be    = (const float*)d_in[7];
    const float* dW    = (const float*)d_in[8];
    const float* db    = (const float*)d_in[9];
    const float* uW    = (const float*)d_in[10];
    const float* ub    = (const float*)d_in[11];
    const float* pW    = (const float*)d_in[12];
    const float* pwb   = (const float*)d_in[13];
    const float* pb    = (const float*)d_in[14];
    const float* phi   = (const float*)d_in[15];
    const float* agWg  = (const float*)d_in[16];
    const float* agbg  = (const float*)d_in[17];
    const float* agWs  = (const float*)d_in[18];
    const float* agbs  = (const float*)d_in[19];
    const float* agWp  = (const float*)d_in[20];
    const float* agbp  = (const float*)d_in[21];

    float *X0, *X1d, *X2d, *Xb, *X1, *X2, *G, *Xu1, *Xu0, *cat;
    float *h1, *e, *eh, *sc, *vals0, *vals1, *catW, *biasGS;
    int *idx0, *idx1;
    unsigned* bm;
    cudaGetSymbolAddress((void**)&X0,  g_X0);
    cudaGetSymbolAddress((void**)&X1d, g_X1d);
    cudaGetSymbolAddress((void**)&X2d, g_X2d);
    cudaGetSymbolAddress((void**)&Xb,  g_Xb);
    cudaGetSymbolAddress((void**)&X1,  g_X1);
    cudaGetSymbolAddress((void**)&X2,  g_X2);
    cudaGetSymbolAddress((void**)&G,   g_G);
    cudaGetSymbolAddress((void**)&Xu1, g_Xu1);
    cudaGetSymbolAddress((void**)&Xu0, g_Xu0);
    cudaGetSymbolAddress((void**)&cat, g_cat);
    cudaGetSymbolAddress((void**)&bm,  g_bm);
    cudaGetSymbolAddress((void**)&h1,  g_h1);
    cudaGetSymbolAddress((void**)&e,   g_e);
    cudaGetSymbolAddress((void**)&eh,  g_eh);
    cudaGetSymbolAddress((void**)&sc,  g_sc);
    cudaGetSymbolAddress((void**)&vals0, g_vals0);
    cudaGetSymbolAddress((void**)&vals1, g_vals1);
    cudaGetSymbolAddress((void**)&idx0, g_idx0);
    cudaGetSymbolAddress((void**)&idx1, g_idx1);
    cudaGetSymbolAddress((void**)&catW, g_catW);
    cudaGetSymbolAddress((void**)&biasGS, g_biasGS);

    const int WMAT = DD * DD;   // 102400

    auto gemm = [&](int M, int N, int K,
                    const float* Ap, int lda, const float* Bp, int ldb,
                    const float* bias, float* Cp, int ldc,
                    const float* res, int ldres, int act) {
        dim3 grid(N / TBN, (M + TBM - 1) / TBM);
        gemm_kernel<<<grid, 256>>>(M, N, K, Ap, lda, Bp, ldb, bias, Cp, ldc, res, ldres, act);
    };

    // ---- setup: adjacency bitmask, concat weights, summed gate biases ----
    build_mask_kernel<<<(N0 * N0) / 256, 256>>>(A, bm);
    add_bias_kernel<<<3, 256>>>(agbg, agbs, biasGS, 2 * DD);
    cudaMemcpyAsync(catW,            agWg,        WMAT * 4, cudaMemcpyDeviceToDevice, 0);
    cudaMemcpyAsync(catW + WMAT,     agWs,        WMAT * 4, cudaMemcpyDeviceToDevice, 0);
    cudaMemcpyAsync(catW + 2 * WMAT, agWg + WMAT, WMAT * 4, cudaMemcpyDeviceToDevice, 0);
    cudaMemcpyAsync(catW + 3 * WMAT, agWs + WMAT, WMAT * 4, cudaMemcpyDeviceToDevice, 0);

    // ---- encoder / down path ----
    gemm(N0, DD, DD, Xin, DD, W0, DD, b0, X0, DD, nullptr, 0, 1);          // start
    gemm(N0, DD, DD, X0, DD, dW, DD, db, X1d, DD, nullptr, 0, 1);          // downs[0]

    gemv_kernel<<<(N0 + 7) / 8, 256>>>(N0, X1d, pW, pwb, pb, h1);
    compute_e_kernel<<<(N0 + 255) / 256, 256>>>(N0, h1, phi, e, eh);
    agg0_kernel<<<N0, 128>>>(bm, e, eh, sc);
    rank_select_kernel<<<(N0 + 255) / 256, 256>>>(sc, N0, KK0, idx0, vals0);
    gather_scale_kernel<<<(KK0 * DD + 255) / 256, 256>>>(X1d, idx0, vals0, KK0, X1);

    gemm(KK0, DD, DD, X1, DD, dW + WMAT, DD, db + DD, X2d, DD, nullptr, 0, 1);  // downs[1]

    gemv_kernel<<<(KK0 + 7) / 8, 256>>>(KK0, X2d, pW + DD, pwb + 1, pb + 1, h1);
    compute_e_kernel<<<(KK0 + 255) / 256, 256>>>(KK0, h1, phi + 2, e, eh);
    agg1_kernel<<<KK0, 256>>>(bm, idx0, KK0, e, eh, sc);
    rank_select_kernel<<<(KK0 + 255) / 256, 256>>>(sc, KK0, KK1, idx1, vals1);
    gather_scale_kernel<<<(KK1 * DD + 255) / 256, 256>>>(X2d, idx1, vals1, KK1, X2);

    gemm(KK1, DD, DD, X2, DD, Wb, DD, bb, Xb, DD, nullptr, 0, 1);          // bottleneck

    // ---- up level i=0 (u=1, n=KK0) ----
    zero_kernel<<<(KK0 * DD2 + 255) / 256, 256>>>(cat, KK0 * DD2);
    scatter_kernel<<<(KK1 * DD + 255) / 256, 256>>>(cat, DD2, idx1, Xb, KK1);
    copy_block_kernel<<<(KK0 * DD + 255) / 256, 256>>>(cat + DD, DD2, X2d, DD, KK0);
    gemm(KK0, DD, DD2, cat, DD2, catW, DD, biasGS, G, DD, nullptr, 0, 1);
    gemm(KK0, DD, DD,  G,   DD,  agWp, DD, agbp, cat + DD, DD2, nullptr, 0, 2);
    gemm(KK0, DD, DD2, cat, DD2, uW,   DD, ub,   Xu1, DD, X2d, DD, 1);

    // ---- up level i=1 (u=0, n=N0) ----
    zero_kernel<<<(N0 * DD2 + 255) / 256, 256>>>(cat, N0 * DD2);
    scatter_kernel<<<(KK0 * DD + 255) / 256, 256>>>(cat, DD2, idx0, Xu1, KK0);
    copy_block_kernel<<<(N0 * DD + 255) / 256, 256>>>(cat + DD, DD2, X1d, DD, N0);
    gemm(N0, DD, DD2, cat, DD2, catW + 2 * WMAT, DD, biasGS + DD, G, DD, nullptr, 0, 1);
    gemm(N0, DD, DD,  G,   DD,  agWp + WMAT, DD, agbp + DD, cat + DD, DD2, nullptr, 0, 2);
    gemm(N0, DD, DD2, cat, DD2, uW + 2 * WMAT, DD, ub + DD, Xu0, DD, X1d, DD, 1);

    // ---- head: out = relu([Xu0, X0] @ We + be), then append start ----
    copy_block_kernel<<<(N0 * DD + 255) / 256, 256>>>(cat,      DD2, Xu0, DD, N0);
    copy_block_kernel<<<(N0 * DD + 255) / 256, 256>>>(cat + DD, DD2, X0,  DD, N0);
    gemm(N0, DD, DD2, cat, DD2, We, DD, be, (float*)d_out, DD, nullptr, 0, 1);

    if (out_size >= 2 * N0 * DD) {
        cudaMemcpyAsync((float*)d_out + (size_t)N0 * DD, X0,
                        (size_t)N0 * DD * sizeof(float), cudaMemcpyDeviceToDevice, 0);
    }
}

// round 2
// speedup vs baseline: 1.0108x; 1.0108x over previous
#include <cuda_runtime.h>
#include <math.h>

// ---------------------------------------------------------------------------
// GraphUnet: N=4096, DIM=320, L=2, KS=(0.8,0.6) -> kk0=3276, kk1=1965
// ---------------------------------------------------------------------------
#define N0   4096
#define DD   320
#define DD2  640
#define KK0  3276
#define KK1  1965
#define NW   128          // bitmask words per row (4096/32)

// ---------------- static scratch (no allocations allowed) ------------------
__device__ float    g_X0 [N0*DD];
__device__ float    g_X1d[N0*DD];
__device__ float    g_X2d[N0*DD];
__device__ float    g_Xb [N0*DD];
__device__ float    g_X1 [N0*DD];
__device__ float    g_X2 [N0*DD];
__device__ float    g_G  [N0*DD];
__device__ float    g_Xu1[N0*DD];
__device__ float    g_Xu0[N0*DD];
__device__ float    g_cat[N0*DD2];
__device__ unsigned g_bm [N0*NW];
__device__ float    g_h1 [N0];
__device__ float    g_e  [N0];
__device__ float    g_eh [N0];
__device__ float    g_sc [N0];
__device__ float    g_vals0[N0];
__device__ float    g_vals1[N0];
__device__ int      g_idx0[N0];
__device__ int      g_idx1[N0];
__device__ float    g_catW[2*DD2*DD];
__device__ float    g_biasGS[2*DD];

// ---------------------------------------------------------------------------
// Packed fp32x2 FMA (Blackwell; bit-exact fp32, 2 MACs/inst)
// ---------------------------------------------------------------------------
__device__ __forceinline__ unsigned long long ffma2(unsigned long long a,
                                                    unsigned long long b,
                                                    unsigned long long c) {
    unsigned long long d;
    asm("fma.rn.f32x2 %0, %1, %2, %3;" : "=l"(d) : "l"(a), "l"(b), "l"(c));
    return d;
}
__device__ __forceinline__ unsigned long long pack2(float x) {
    unsigned long long d;
    asm("mov.b64 %0, {%1, %1};" : "=l"(d) : "f"(x));
    return d;
}
union F2U { unsigned long long u; float2 f; };

// ---------------------------------------------------------------------------
// Bitmask build
// ---------------------------------------------------------------------------
__global__ void build_mask_kernel(const float* __restrict__ A, unsigned* __restrict__ bm) {
    int gid = blockIdx.x * blockDim.x + threadIdx.x;
    float v = A[gid];
    unsigned b = __ballot_sync(0xffffffffu, v != 0.0f);
    if ((threadIdx.x & 31) == 0) bm[gid >> 5] = b;
}

// ---------------------------------------------------------------------------
// FP32 GEMM with f32x2 packed FMA, double-buffered smem.
// C[M,64*gx] = act(A[M,K] @ B[K,N] + bias) (+res after act)
// BMT in {128, 64}; BN=64; BK=16; 256 threads.
// N multiple of 64, K multiple of 16. act: 0 none, 1 relu, 2 sigmoid.
// ---------------------------------------------------------------------------
template<int BMT>
__global__ __launch_bounds__(256) void gemm2_kernel(
    int M, int K,
    const float* __restrict__ A, int lda,
    const float* __restrict__ B, int ldb,
    const float* __restrict__ bias,
    float* __restrict__ C, int ldc,
    const float* __restrict__ res, int ldres,
    int act)
{
    constexpr int SA  = BMT + 4;         // padded row stride for As
    constexpr int AF4 = BMT / 64;        // float4 A-loads per thread (2 or 1)
    constexpr int NP  = BMT / 32;        // row-pairs per thread (4 or 2)

    __shared__ float As[2][16][SA];
    __shared__ float Bs[2][16][64];

    const int tid  = threadIdx.x;
    const int tx   = tid & 15;           // col group 0..15 -> cols tx*4
    const int ty   = tid >> 4;           // row group 0..15 -> rows ty*4 (+64)
    const int row0 = blockIdx.y * BMT;
    const int col0 = blockIdx.x * 64;

    // A tile load map (transpose into As[k][m])
    const int am = (AF4 == 2) ? (tid >> 1) : (tid >> 2);
    const int ak = (AF4 == 2) ? ((tid & 1) * 8) : ((tid & 3) * 4);
    // B tile load map (direct)
    const int bk = tid >> 4;
    const int bn = (tid & 15) * 4;

    unsigned long long acc[NP][4];
#pragma unroll
    for (int p = 0; p < NP; p++)
#pragma unroll
        for (int j = 0; j < 4; j++) acc[p][j] = 0ull;

    const int nt = K / 16;

    // ---- prologue: tile 0 -> buffer 0 ----
    {
        const int gm = row0 + am;
#pragma unroll
        for (int f = 0; f < AF4; f++) {
            float4 v = make_float4(0.f, 0.f, 0.f, 0.f);
            if (gm < M)
                v = *reinterpret_cast<const float4*>(A + (size_t)gm * lda + ak + f * 4);
            As[0][ak + f * 4 + 0][am] = v.x;
            As[0][ak + f * 4 + 1][am] = v.y;
            As[0][ak + f * 4 + 2][am] = v.z;
            As[0][ak + f * 4 + 3][am] = v.w;
        }
        float4 bv = *reinterpret_cast<const float4*>(B + (size_t)bk * ldb + col0 + bn);
        *reinterpret_cast<float4*>(&Bs[0][bk][bn]) = bv;
    }
    __syncthreads();

    int buf = 0;
    for (int it = 0; it < nt; ++it) {
        // prefetch next tile into registers
        float4 ra[AF4];
        float4 rb;
        const bool has = (it + 1 < nt);
        if (has) {
            const int k0 = (it + 1) * 16;
            const int gm = row0 + am;
#pragma unroll
            for (int f = 0; f < AF4; f++) {
                ra[f] = make_float4(0.f, 0.f, 0.f, 0.f);
                if (gm < M)
                    ra[f] = *reinterpret_cast<const float4*>(A + (size_t)gm * lda + k0 + ak + f * 4);
            }
            rb = *reinterpret_cast<const float4*>(B + (size_t)(k0 + bk) * ldb + col0 + bn);
        }

        // compute 16 k-steps from smem[buf]
#pragma unroll
        for (int kk = 0; kk < 16; kk++) {
            float4 b4 = *reinterpret_cast<const float4*>(&Bs[buf][kk][tx * 4]);
            unsigned long long bb0 = pack2(b4.x);
            unsigned long long bb1 = pack2(b4.y);
            unsigned long long bb2 = pack2(b4.z);
            unsigned long long bb3 = pack2(b4.w);

            ulonglong2 aA = *reinterpret_cast<const ulonglong2*>(&As[buf][kk][ty * 4]);
            acc[0][0] = ffma2(aA.x, bb0, acc[0][0]);
            acc[0][1] = ffma2(aA.x, bb1, acc[0][1]);
            acc[0][2] = ffma2(aA.x, bb2, acc[0][2]);
            acc[0][3] = ffma2(aA.x, bb3, acc[0][3]);
            acc[1][0] = ffma2(aA.y, bb0, acc[1][0]);
            acc[1][1] = ffma2(aA.y, bb1, acc[1][1]);
            acc[1][2] = ffma2(aA.y, bb2, acc[1][2]);
            acc[1][3] = ffma2(aA.y, bb3, acc[1][3]);
            if (NP == 4) {
                ulonglong2 aB = *reinterpret_cast<const ulonglong2*>(&As[buf][kk][ty * 4 + 64]);
                acc[2][0] = ffma2(aB.x, bb0, acc[2][0]);
                acc[2][1] = ffma2(aB.x, bb1, acc[2][1]);
                acc[2][2] = ffma2(aB.x, bb2, acc[2][2]);
                acc[2][3] = ffma2(aB.x, bb3, acc[2][3]);
                acc[3][0] = ffma2(aB.y, bb0, acc[3][0]);
                acc[3][1] = ffma2(aB.y, bb1, acc[3][1]);
                acc[3][2] = ffma2(aB.y, bb2, acc[3][2]);
                acc[3][3] = ffma2(aB.y, bb3, acc[3][3]);
            }
        }

        if (has) {
            const int nb = buf ^ 1;
#pragma unroll
            for (int f = 0; f < AF4; f++) {
                As[nb][ak + f * 4 + 0][am] = ra[f].x;
                As[nb][ak + f * 4 + 1][am] = ra[f].y;
                As[nb][ak + f * 4 + 2][am] = ra[f].z;
                As[nb][ak + f * 4 + 3][am] = ra[f].w;
            }
            *reinterpret_cast<float4*>(&Bs[nb][bk][bn]) = rb;
            __syncthreads();
            buf = nb;
        }
    }

    // ---- epilogue ----
    const int cb = col0 + tx * 4;
    float bv0 = bias[cb + 0], bv1 = bias[cb + 1], bv2 = bias[cb + 2], bv3 = bias[cb + 3];
#pragma unroll
    for (int p = 0; p < NP; p++) {
        const int r0 = row0 + ty * 4 + (p & 1) * 2 + (p >> 1) * 64;
#pragma unroll
        for (int h = 0; h < 2; h++) {
            const int r = r0 + h;
            if (r >= M) continue;
            float v[4];
#pragma unroll
            for (int j = 0; j < 4; j++) {
                F2U u; u.u = acc[p][j];
                v[j] = (h ? u.f.y : u.f.x);
            }
            v[0] += bv0; v[1] += bv1; v[2] += bv2; v[3] += bv3;
            if (act == 1) {
#pragma unroll
                for (int j = 0; j < 4; j++) v[j] = fmaxf(v[j], 0.f);
            } else if (act == 2) {
#pragma unroll
                for (int j = 0; j < 4; j++) v[j] = 1.f / (1.f + expf(-v[j]));
            }
            if (res) {
#pragma unroll
                for (int j = 0; j < 4; j++) v[j] += res[(size_t)r * ldres + cb + j];
            }
            float* cp = C + (size_t)r * ldc + cb;
            cp[0] = v[0]; cp[1] = v[1]; cp[2] = v[2]; cp[3] = v[3];
        }
    }
}

// ---------------------------------------------------------------------------
// Fused GEMV + e/eh: h1[r] = X[r,:]@w + c;  e=exp(phi0*h1); eh=e*h1
// ---------------------------------------------------------------------------
__global__ void gemv_e_kernel(int M, const float* __restrict__ X,
                              const float* __restrict__ w,
                              const float* __restrict__ pwb,
                              const float* __restrict__ pb,
                              const float* __restrict__ phi0,
                              float* __restrict__ h1,
                              float* __restrict__ e, float* __restrict__ eh)
{
    int warp = (blockIdx.x * blockDim.x + threadIdx.x) >> 5;
    int lane = threadIdx.x & 31;
    if (warp >= M) return;
    const float* xr = X + (size_t)warp * DD;
    float s = 0.f;
    for (int k = lane; k < DD; k += 32) s += xr[k] * w[k];
#pragma unroll
    for (int o = 16; o > 0; o >>= 1) s += __shfl_down_sync(0xffffffffu, s, o);
    if (lane == 0) {
        float h = s + pwb[0] + pb[0];
        float ex = expf(phi0[0] * h);
        h1[warp] = h;
        e[warp] = ex;
        eh[warp] = ex * h;
    }
}

// Level-0 aggregation: block per row, 128 threads (1 word each).
__global__ void agg0_kernel(const unsigned* __restrict__ bm,
                            const float* __restrict__ e,
                            const float* __restrict__ eh,
                            float* __restrict__ scores)
{
    int r = blockIdx.x;
    int t = threadIdx.x;
    unsigned w = bm[r * NW + t];
    if ((r >> 5) == t) w |= (1u << (r & 31));
    float se = 0.f, sh = 0.f;
    while (w) {
        int b = __ffs(w) - 1;
        w &= w - 1;
        int j = t * 32 + b;
        se += e[j];
        sh += eh[j];
    }
    __shared__ float s1[128], s2[128];
    s1[t] = se; s2[t] = sh;
    __syncthreads();
    for (int o = 64; o > 0; o >>= 1) {
        if (t < o) { s1[t] += s1[t + o]; s2[t] += s2[t + o]; }
        __syncthreads();
    }
    if (t == 0) {
        float agg = (s2[0] / s1[0]) * 0.01f;
        scores[r] = 1.f / (1.f + expf(-agg));
    }
}

// Level-1 aggregation over A[idx0][:,idx0]
__global__ void agg1_kernel(const unsigned* __restrict__ bm,
                            const int* __restrict__ idx0, int n1,
                            const float* __restrict__ e,
                            const float* __restrict__ eh,
                            float* __restrict__ scores)
{
    __shared__ unsigned row[NW];
    int r = blockIdx.x;
    int t = threadIdx.x;
    int orig = idx0[r];
    if (t < NW) row[t] = bm[orig * NW + t];
    __syncthreads();
    float se = 0.f, sh = 0.f;
    for (int j = t; j < n1; j += 256) {
        int c = idx0[j];
        bool in = (row[c >> 5] >> (c & 31)) & 1u;
        if (j == r) in = true;
        if (in) { se += e[j]; sh += eh[j]; }
    }
    __shared__ float s1[256], s2[256];
    s1[t] = se; s2[t] = sh;
    __syncthreads();
    for (int o = 128; o > 0; o >>= 1) {
        if (t < o) { s1[t] += s1[t + o]; s2[t] += s2[t + o]; }
        __syncthreads();
    }
    if (t == 0) {
        float agg = (s2[0] / s1[0]) * 0.01f;
        scores[r] = 1.f / (1.f + expf(-agg));
    }
}

// Stable top-k by full rank (matches jax.lax.top_k order exactly)
__global__ void rank_select_kernel(const float* __restrict__ s, int n, int kk,
                                   int* __restrict__ idx, float* __restrict__ vals)
{
    __shared__ float sh[256];
    int i = blockIdx.x * blockDim.x + threadIdx.x;
    float si = (i < n) ? s[i] : 0.f;
    int rank = 0;
    for (int base = 0; base < n; base += 256) {
        int j = base + threadIdx.x;
        sh[threadIdx.x] = (j < n) ? s[j] : -3.0e38f;
        __syncthreads();
        int lim = min(256, n - base);
        for (int t = 0; t < lim; t++) {
            float sj = sh[t];
            int j2 = base + t;
            if (sj > si || (sj == si && j2 < i)) rank++;
        }
        __syncthreads();
    }
    if (i < n && rank < kk) { idx[rank] = i; vals[rank] = si; }
}

__global__ void gather_scale_kernel(const float* __restrict__ src,
                                    const int* __restrict__ idx,
                                    const float* __restrict__ vals,
                                    int rows, float* __restrict__ dst)
{
    int gid = blockIdx.x * blockDim.x + threadIdx.x;
    if (gid >= rows * DD) return;
    int r = gid / DD, c = gid % DD;
    dst[gid] = src[(size_t)idx[r] * DD + c] * vals[r];
}

__global__ void zero_kernel(float* __restrict__ p, int n) {
    int gid = blockIdx.x * blockDim.x + threadIdx.x;
    if (gid < n) p[gid] = 0.f;
}

__global__ void scatter_kernel(float* __restrict__ dst, int ldd,
                               const int* __restrict__ idx,
                               const float* __restrict__ src, int rows)
{
    int gid = blockIdx.x * blockDim.x + threadIdx.x;
    if (gid >= rows * DD) return;
    int r = gid / DD, c = gid % DD;
    dst[(size_t)idx[r] * ldd + c] = src[gid];
}

__global__ void copy_block_kernel(float* __restrict__ dst, int ldd,
                                  const float* __restrict__ src, int lds, int rows)
{
    int gid = blockIdx.x * blockDim.x + threadIdx.x;
    if (gid >= rows * DD) return;
    int r = gid / DD, c = gid % DD;
    dst[(size_t)r * ldd + c] = src[(size_t)r * lds + c];
}

__global__ void add_bias_kernel(const float* __restrict__ a,
                                const float* __restrict__ b,
                                float* __restrict__ o, int n)
{
    int gid = blockIdx.x * blockDim.x + threadIdx.x;
    if (gid < n) o[gid] = a[gid] + b[gid];
}

// ---------------------------------------------------------------------------
extern "C" void kernel_launch(void* const* d_in, const int* in_sizes, int n_in,
                              void* d_out, int out_size)
{
    const float* A     = (const float*)d_in[0];
    const float* Xin   = (const float*)d_in[1];
    const float* W0    = (const float*)d_in[2];
    const float* b0    = (const float*)d_in[3];
    const float* Wb    = (const float*)d_in[4];
    const float* bb    = (const float*)d_in[5];
    const float* We    = (const float*)d_in[6];
    const float* be    = (const float*)d_in[7];
    const float* dW    = (const float*)d_in[8];
    const float* db    = (const float*)d_in[9];
    const float* uW    = (const float*)d_in[10];
    const float* ub    = (const float*)d_in[11];
    const float* pW    = (const float*)d_in[12];
    const float* pwb   = (const float*)d_in[13];
    const float* pb    = (const float*)d_in[14];
    const float* phi   = (const float*)d_in[15];
    const float* agWg  = (const float*)d_in[16];
    const float* agbg  = (const float*)d_in[17];
    const float* agWs  = (const float*)d_in[18];
    const float* agbs  = (const float*)d_in[19];
    const float* agWp  = (const float*)d_in[20];
    const float* agbp  = (const float*)d_in[21];

    float *X0, *X1d, *X2d, *Xb, *X1, *X2, *G, *Xu1, *Xu0, *cat;
    float *h1, *e, *eh, *sc, *vals0, *vals1, *catW, *biasGS;
    int *idx0, *idx1;
    unsigned* bm;
    cudaGetSymbolAddress((void**)&X0,  g_X0);
    cudaGetSymbolAddress((void**)&X1d, g_X1d);
    cudaGetSymbolAddress((void**)&X2d, g_X2d);
    cudaGetSymbolAddress((void**)&Xb,  g_Xb);
    cudaGetSymbolAddress((void**)&X1,  g_X1);
    cudaGetSymbolAddress((void**)&X2,  g_X2);
    cudaGetSymbolAddress((void**)&G,   g_G);
    cudaGetSymbolAddress((void**)&Xu1, g_Xu1);
    cudaGetSymbolAddress((void**)&Xu0, g_Xu0);
    cudaGetSymbolAddress((void**)&cat, g_cat);
    cudaGetSymbolAddress((void**)&bm,  g_bm);
    cudaGetSymbolAddress((void**)&h1,  g_h1);
    cudaGetSymbolAddress((void**)&e,   g_e);
    cudaGetSymbolAddress((void**)&eh,  g_eh);
    cudaGetSymbolAddress((void**)&sc,  g_sc);
    cudaGetSymbolAddress((void**)&vals0, g_vals0);
    cudaGetSymbolAddress((void**)&vals1, g_vals1);
    cudaGetSymbolAddress((void**)&idx0, g_idx0);
    cudaGetSymbolAddress((void**)&idx1, g_idx1);
    cudaGetSymbolAddress((void**)&catW, g_catW);
    cudaGetSymbolAddress((void**)&biasGS, g_biasGS);

    const int WMAT = DD * DD;   // 102400

    auto gemm = [&](int M, int N, int K,
                    const float* Ap, int lda, const float* Bp, int ldb,
                    const float* bias, float* Cp, int ldc,
                    const float* res, int ldres, int act) {
        if (M >= 2048) {
            dim3 grid(N / 64, (M + 127) / 128);
            gemm2_kernel<128><<<grid, 256>>>(M, K, Ap, lda, Bp, ldb, bias, Cp, ldc, res, ldres, act);
        } else {
            dim3 grid(N / 64, (M + 63) / 64);
            gemm2_kernel<64><<<grid, 256>>>(M, K, Ap, lda, Bp, ldb, bias, Cp, ldc, res, ldres, act);
        }
    };

    // ---- setup ----
    build_mask_kernel<<<(N0 * N0) / 256, 256>>>(A, bm);
    add_bias_kernel<<<3, 256>>>(agbg, agbs, biasGS, 2 * DD);
    cudaMemcpyAsync(catW,            agWg,        WMAT * 4, cudaMemcpyDeviceToDevice, 0);
    cudaMemcpyAsync(catW + WMAT,     agWs,        WMAT * 4, cudaMemcpyDeviceToDevice, 0);
    cudaMemcpyAsync(catW + 2 * WMAT, agWg + WMAT, WMAT * 4, cudaMemcpyDeviceToDevice, 0);
    cudaMemcpyAsync(catW + 3 * WMAT, agWs + WMAT, WMAT * 4, cudaMemcpyDeviceToDevice, 0);

    // ---- encoder / down path ----
    gemm(N0, DD, DD, Xin, DD, W0, DD, b0, X0, DD, nullptr, 0, 1);
    gemm(N0, DD, DD, X0, DD, dW, DD, db, X1d, DD, nullptr, 0, 1);

    gemv_e_kernel<<<(N0 + 7) / 8, 256>>>(N0, X1d, pW, pwb, pb, phi, h1, e, eh);
    agg0_kernel<<<N0, 128>>>(bm, e, eh, sc);
    rank_select_kernel<<<(N0 + 255) / 256, 256>>>(sc, N0, KK0, idx0, vals0);
    gather_scale_kernel<<<(KK0 * DD + 255) / 256, 256>>>(X1d, idx0, vals0, KK0, X1);

    gemm(KK0, DD, DD, X1, DD, dW + WMAT, DD, db + DD, X2d, DD, nullptr, 0, 1);

    gemv_e_kernel<<<(KK0 + 7) / 8, 256>>>(KK0, X2d, pW + DD, pwb + 1, pb + 1, phi + 2, h1, e, eh);
    agg1_kernel<<<KK0, 256>>>(bm, idx0, KK0, e, eh, sc);
    rank_select_kernel<<<(KK0 + 255) / 256, 256>>>(sc, KK0, KK1, idx1, vals1);
    gather_scale_kernel<<<(KK1 * DD + 255) / 256, 256>>>(X2d, idx1, vals1, KK1, X2);

    gemm(KK1, DD, DD, X2, DD, Wb, DD, bb, Xb, DD, nullptr, 0, 1);

    // ---- up level i=0 (u=1, n=KK0) ----
    zero_kernel<<<(KK0 * DD2 + 255) / 256, 256>>>(cat, KK0 * DD2);
    scatter_kernel<<<(KK1 * DD + 255) / 256, 256>>>(cat, DD2, idx1, Xb, KK1);
    copy_block_kernel<<<(KK0 * DD + 255) / 256, 256>>>(cat + DD, DD2, X2d, DD, KK0);
    gemm(KK0, DD, DD2, cat, DD2, catW, DD, biasGS, G, DD, nullptr, 0, 1);
    gemm(KK0, DD, DD,  G,   DD,  agWp, DD, agbp, cat + DD, DD2, nullptr, 0, 2);
    gemm(KK0, DD, DD2, cat, DD2, uW,   DD, ub,   Xu1, DD, X2d, DD, 1);

    // ---- up level i=1 (u=0, n=N0) ----
    zero_kernel<<<(N0 * DD2 + 255) / 256, 256>>>(cat, N0 * DD2);
    scatter_kernel<<<(KK0 * DD + 255) / 256, 256>>>(cat, DD2, idx0, Xu1, KK0);
    copy_block_kernel<<<(N0 * DD + 255) / 256, 256>>>(cat + DD, DD2, X1d, DD, N0);
    gemm(N0, DD, DD2, cat, DD2, catW + 2 * WMAT, DD, biasGS + DD, G, DD, nullptr, 0, 1);
    gemm(N0, DD, DD,  G,   DD,  agWp + WMAT, DD, agbp + DD, cat + DD, DD2, nullptr, 0, 2);
    gemm(N0, DD, DD2, cat, DD2, uW + 2 * WMAT, DD, ub + DD, Xu0, DD, X1d, DD, 1);

    // ---- head ----
    copy_block_kernel<<<(N0 * DD + 255) / 256, 256>>>(cat,      DD2, Xu0, DD, N0);
    copy_block_kernel<<<(N0 * DD + 255) / 256, 256>>>(cat + DD, DD2, X0,  DD, N0);
    gemm(N0, DD, DD2, cat, DD2, We, DD, be, (float*)d_out, DD, nullptr, 0, 1);

    if (out_size >= 2 * N0 * DD) {
        cudaMemcpyAsync((float*)d_out + (size_t)N0 * DD, X0,
                        (size_t)N0 * DD * sizeof(float), cudaMemcpyDeviceToDevice, 0);
    }
}

// round 3
// speedup vs baseline: 1.3154x; 1.3014x over previous
#include <cuda_runtime.h>
#include <math.h>

// ---------------------------------------------------------------------------
// GraphUnet: N=4096, DIM=320, L=2, KS=(0.8,0.6) -> kk0=3276, kk1=1965
// ---------------------------------------------------------------------------
#define N0   4096
#define DD   320
#define DD2  640
#define KK0  3276
#define KK1  1965
#define NW   128          // bitmask words per row (4096/32)

// ---------------- static scratch (no allocations allowed) ------------------
__device__ float    g_X0 [N0*DD];
__device__ float    g_X1d[N0*DD];
__device__ float    g_X2d[N0*DD];
__device__ float    g_Xb [N0*DD];
__device__ float    g_X1 [N0*DD];
__device__ float    g_X2 [N0*DD];
__device__ float    g_G  [N0*DD];
__device__ float    g_Xu1[N0*DD];
__device__ float    g_Xu0[N0*DD];
__device__ float    g_cat[N0*DD2];
__device__ unsigned g_bm [N0*NW];
__device__ float    g_h1 [N0];
__device__ float    g_e  [N0];
__device__ float    g_eh [N0];
__device__ float    g_sc [N0];
__device__ float    g_vals0[N0];
__device__ float    g_vals1[N0];
__device__ int      g_idx0[N0];
__device__ int      g_idx1[N0];
__device__ float    g_catW[2*DD2*DD];
__device__ float    g_biasGS[2*DD];

// ---------------------------------------------------------------------------
// helpers
// ---------------------------------------------------------------------------
__device__ __forceinline__ unsigned tf32_rna(float x) {
    unsigned r;
    asm("cvt.rna.tf32.f32 %0, %1;" : "=r"(r) : "f"(x));
    return r;
}

__device__ __forceinline__ void mma_tf32(float* d, const unsigned* a, const unsigned* b) {
    asm volatile(
        "mma.sync.aligned.m16n8k8.row.col.f32.tf32.tf32.f32 "
        "{%0,%1,%2,%3}, {%4,%5,%6,%7}, {%8,%9}, {%0,%1,%2,%3};"
        : "+f"(d[0]), "+f"(d[1]), "+f"(d[2]), "+f"(d[3])
        : "r"(a[0]), "r"(a[1]), "r"(a[2]), "r"(a[3]), "r"(b[0]), "r"(b[1]));
}

__device__ __forceinline__ void cp_async16(unsigned daddr, const void* gptr, int src_bytes) {
    asm volatile("cp.async.cg.shared.global [%0], [%1], 16, %2;"
                 :: "r"(daddr), "l"(gptr), "r"(src_bytes));
}

// ---------------------------------------------------------------------------
// Bitmask build
// ---------------------------------------------------------------------------
__global__ void build_mask_kernel(const float* __restrict__ A, unsigned* __restrict__ bm) {
    int gid = blockIdx.x * blockDim.x + threadIdx.x;
    float v = A[gid];
    unsigned b = __ballot_sync(0xffffffffu, v != 0.0f);
    if ((threadIdx.x & 31) == 0) bm[gid >> 5] = b;
}

// ---------------------------------------------------------------------------
// 3xTF32 tensor-core GEMM.
// C[M,N] = act(A[M,K] @ B[K,N] + bias) (+res after act)
// CTA: 128 threads (4 warps 2x2), tile 64x64, BK=32, cp.async 2-stage.
// N multiple of 64, K multiple of 32. act: 0 none, 1 relu, 2 sigmoid.
// ---------------------------------------------------------------------------
#define APITCH 36
#define BPITCH 72

__global__ __launch_bounds__(128) void gemm_tc_kernel(
    int M, int K,
    const float* __restrict__ A, int lda,
    const float* __restrict__ B, int ldb,
    const float* __restrict__ bias,
    float* __restrict__ C, int ldc,
    const float* __restrict__ res, int ldres,
    int act)
{
    __shared__ float As[2][64][APITCH];
    __shared__ float Bs[2][32][BPITCH];

    const int tid  = threadIdx.x;
    const int wid  = tid >> 5;
    const int lane = tid & 31;
    const int wm   = wid & 1;           // warp row (0..1) -> rows wm*32
    const int wn   = wid >> 1;          // warp col (0..1) -> cols wn*32
    const int g    = lane >> 2;         // 0..7
    const int tg   = lane & 3;          // 0..3

    const int row0 = blockIdx.y * 64;
    const int col0 = blockIdx.x * 64;

    unsigned asBase = (unsigned)__cvta_generic_to_shared(&As[0][0][0]);
    unsigned bsBase = (unsigned)__cvta_generic_to_shared(&Bs[0][0][0]);

    float acc[2][4][4];
#pragma unroll
    for (int mt = 0; mt < 2; mt++)
#pragma unroll
        for (int nt = 0; nt < 4; nt++)
#pragma unroll
            for (int j = 0; j < 4; j++) acc[mt][nt][j] = 0.f;

    const int nt_k = K / 32;

    auto issue_stage = [&](int kt, int s) {
        const int k0 = kt * 32;
        // A tile: 64x32 = 512 float4, 4 per thread
#pragma unroll
        for (int i = 0; i < 4; i++) {
            int idx = i * 128 + tid;
            int r = idx >> 3, c4 = idx & 7;
            int gr = row0 + r;
            int pr = (gr < M) ? 16 : 0;
            int grc = gr < M ? gr : (M - 1);
            const float* gp = A + (size_t)grc * lda + k0 + c4 * 4;
            unsigned daddr = asBase + (unsigned)(((s * 64 + r) * APITCH + c4 * 4) * 4);
            cp_async16(daddr, gp, pr);
        }
        // B tile: 32x64 = 512 float4, 4 per thread
#pragma unroll
        for (int i = 0; i < 4; i++) {
            int idx = i * 128 + tid;
            int kr = idx >> 4, c4 = idx & 15;
            const float* gp = B + (size_t)(k0 + kr) * ldb + col0 + c4 * 4;
            unsigned daddr = bsBase + (unsigned)(((s * 32 + kr) * BPITCH + c4 * 4) * 4);
            cp_async16(daddr, gp, 16);
        }
        asm volatile("cp.async.commit_group;");
    };

    issue_stage(0, 0);

    for (int kt = 0; kt < nt_k; kt++) {
        asm volatile("cp.async.wait_group 0;");
        __syncthreads();
        if (kt + 1 < nt_k) issue_stage(kt + 1, (kt + 1) & 1);

        const int buf = kt & 1;
        const float(*Asb)[APITCH] = As[buf];
        const float(*Bsb)[BPITCH] = Bs[buf];

#pragma unroll
        for (int kk = 0; kk < 4; kk++) {
            const int kc = kk * 8;
            unsigned abg[2][4], asm2[2][4];
#pragma unroll
            for (int mt = 0; mt < 2; mt++) {
                const int rb = wm * 32 + mt * 16;
                float x0 = Asb[rb + g][kc + tg];
                float x1 = Asb[rb + g + 8][kc + tg];
                float x2 = Asb[rb + g][kc + tg + 4];
                float x3 = Asb[rb + g + 8][kc + tg + 4];
                abg[mt][0] = tf32_rna(x0);
                abg[mt][1] = tf32_rna(x1);
                abg[mt][2] = tf32_rna(x2);
                abg[mt][3] = tf32_rna(x3);
                asm2[mt][0] = tf32_rna(x0 - __uint_as_float(abg[mt][0]));
                asm2[mt][1] = tf32_rna(x1 - __uint_as_float(abg[mt][1]));
                asm2[mt][2] = tf32_rna(x2 - __uint_as_float(abg[mt][2]));
                asm2[mt][3] = tf32_rna(x3 - __uint_as_float(abg[mt][3]));
            }
            unsigned bbg[4][2], bsm[4][2];
#pragma unroll
            for (int nt = 0; nt < 4; nt++) {
                const int cb = wn * 32 + nt * 8;
                float y0 = Bsb[kc + tg][cb + g];
                float y1 = Bsb[kc + tg + 4][cb + g];
                bbg[nt][0] = tf32_rna(y0);
                bbg[nt][1] = tf32_rna(y1);
                bsm[nt][0] = tf32_rna(y0 - __uint_as_float(bbg[nt][0]));
                bsm[nt][1] = tf32_rna(y1 - __uint_as_float(bbg[nt][1]));
            }
#pragma unroll
            for (int mt = 0; mt < 2; mt++)
#pragma unroll
                for (int nt = 0; nt < 4; nt++) {
                    mma_tf32(acc[mt][nt], abg[mt], bbg[nt]);
                    mma_tf32(acc[mt][nt], abg[mt], bsm[nt]);
                    mma_tf32(acc[mt][nt], asm2[mt], bbg[nt]);
                }
        }
        __syncthreads();
    }

    // ---- epilogue ----
#pragma unroll
    for (int mt = 0; mt < 2; mt++) {
#pragma unroll
        for (int nt = 0; nt < 4; nt++) {
            const int col = col0 + wn * 32 + nt * 8 + tg * 2;
            float b0 = bias[col], b1 = bias[col + 1];
#pragma unroll
            for (int h = 0; h < 2; h++) {
                const int r = row0 + wm * 32 + mt * 16 + g + h * 8;
                if (r >= M) continue;
                float v0 = acc[mt][nt][h * 2 + 0] + b0;
                float v1 = acc[mt][nt][h * 2 + 1] + b1;
                if (act == 1) {
                    v0 = fmaxf(v0, 0.f); v1 = fmaxf(v1, 0.f);
                } else if (act == 2) {
                    v0 = 1.f / (1.f + expf(-v0));
                    v1 = 1.f / (1.f + expf(-v1));
                }
                if (res) {
                    v0 += res[(size_t)r * ldres + col];
                    v1 += res[(size_t)r * ldres + col + 1];
                }
                float2* cp = reinterpret_cast<float2*>(C + (size_t)r * ldc + col);
                *cp = make_float2(v0, v1);
            }
        }
    }
}

// ---------------------------------------------------------------------------
// Fused GEMV + e/eh
// ---------------------------------------------------------------------------
__global__ void gemv_e_kernel(int M, const float* __restrict__ X,
                              const float* __restrict__ w,
                              const float* __restrict__ pwb,
                              const float* __restrict__ pb,
                              const float* __restrict__ phi0,
                              float* __restrict__ h1,
                              float* __restrict__ e, float* __restrict__ eh)
{
    int warp = (blockIdx.x * blockDim.x + threadIdx.x) >> 5;
    int lane = threadIdx.x & 31;
    if (warp >= M) return;
    const float* xr = X + (size_t)warp * DD;
    float s = 0.f;
    for (int k = lane; k < DD; k += 32) s += xr[k] * w[k];
#pragma unroll
    for (int o = 16; o > 0; o >>= 1) s += __shfl_down_sync(0xffffffffu, s, o);
    if (lane == 0) {
        float h = s + pwb[0] + pb[0];
        float ex = expf(phi0[0] * h);
        h1[warp] = h;
        e[warp] = ex;
        eh[warp] = ex * h;
    }
}

// Level-0 aggregation
__global__ void agg0_kernel(const unsigned* __restrict__ bm,
                            const float* __restrict__ e,
                            const float* __restrict__ eh,
                            float* __restrict__ scores)
{
    int r = blockIdx.x;
    int t = threadIdx.x;
    unsigned w = bm[r * NW + t];
    if ((r >> 5) == t) w |= (1u << (r & 31));
    float se = 0.f, sh = 0.f;
    while (w) {
        int b = __ffs(w) - 1;
        w &= w - 1;
        int j = t * 32 + b;
        se += e[j];
        sh += eh[j];
    }
    __shared__ float s1[128], s2[128];
    s1[t] = se; s2[t] = sh;
    __syncthreads();
    for (int o = 64; o > 0; o >>= 1) {
        if (t < o) { s1[t] += s1[t + o]; s2[t] += s2[t + o]; }
        __syncthreads();
    }
    if (t == 0) {
        float agg = (s2[0] / s1[0]) * 0.01f;
        scores[r] = 1.f / (1.f + expf(-agg));
    }
}

// Level-1 aggregation
__global__ void agg1_kernel(const unsigned* __restrict__ bm,
                            const int* __restrict__ idx0, int n1,
                            const float* __restrict__ e,
                            const float* __restrict__ eh,
                            float* __restrict__ scores)
{
    __shared__ unsigned row[NW];
    int r = blockIdx.x;
    int t = threadIdx.x;
    int orig = idx0[r];
    if (t < NW) row[t] = bm[orig * NW + t];
    __syncthreads();
    float se = 0.f, sh = 0.f;
    for (int j = t; j < n1; j += 256) {
        int c = idx0[j];
        bool in = (row[c >> 5] >> (c & 31)) & 1u;
        if (j == r) in = true;
        if (in) { se += e[j]; sh += eh[j]; }
    }
    __shared__ float s1[256], s2[256];
    s1[t] = se; s2[t] = sh;
    __syncthreads();
    for (int o = 128; o > 0; o >>= 1) {
        if (t < o) { s1[t] += s1[t + o]; s2[t] += s2[t + o]; }
        __syncthreads();
    }
    if (t == 0) {
        float agg = (s2[0] / s1[0]) * 0.01f;
        scores[r] = 1.f / (1.f + expf(-agg));
    }
}

// Stable top-k by full rank (matches jax.lax.top_k order exactly)
__global__ void rank_select_kernel(const float* __restrict__ s, int n, int kk,
                                   int* __restrict__ idx, float* __restrict__ vals)
{
    __shared__ float sh[256];
    int i = blockIdx.x * blockDim.x + threadIdx.x;
    float si = (i < n) ? s[i] : 0.f;
    int rank = 0;
    for (int base = 0; base < n; base += 256) {
        int j = base + threadIdx.x;
        sh[threadIdx.x] = (j < n) ? s[j] : -3.0e38f;
        __syncthreads();
        int lim = min(256, n - base);
        for (int t = 0; t < lim; t++) {
            float sj = sh[t];
            int j2 = base + t;
            if (sj > si || (sj == si && j2 < i)) rank++;
        }
        __syncthreads();
    }
    if (i < n && rank < kk) { idx[rank] = i; vals[rank] = si; }
}

__global__ void gather_scale_kernel(const float* __restrict__ src,
                                    const int* __restrict__ idx,
                                    const float* __restrict__ vals,
                                    int rows, float* __restrict__ dst)
{
    int gid = blockIdx.x * blockDim.x + threadIdx.x;
    if (gid >= rows * DD) return;
    int r = gid / DD, c = gid % DD;
    dst[gid] = src[(size_t)idx[r] * DD + c] * vals[r];
}

__global__ void zero_kernel(float* __restrict__ p, int n) {
    int gid = blockIdx.x * blockDim.x + threadIdx.x;
    if (gid < n) p[gid] = 0.f;
}

__global__ void scatter_kernel(float* __restrict__ dst, int ldd,
                               const int* __restrict__ idx,
                               const float* __restrict__ src, int rows)
{
    int gid = blockIdx.x * blockDim.x + threadIdx.x;
    if (gid >= rows * DD) return;
    int r = gid / DD, c = gid % DD;
    dst[(size_t)idx[r] * ldd + c] = src[gid];
}

__global__ void copy_block_kernel(float* __restrict__ dst, int ldd,
                                  const float* __restrict__ src, int lds, int rows)
{
    int gid = blockIdx.x * blockDim.x + threadIdx.x;
    if (gid >= rows * DD) return;
    int r = gid / DD, c = gid % DD;
    dst[(size_t)r * ldd + c] = src[(size_t)r * lds + c];
}

__global__ void add_bias_kernel(const float* __restrict__ a,
                                const float* __restrict__ b,
                                float* __restrict__ o, int n)
{
    int gid = blockIdx.x * blockDim.x + threadIdx.x;
    if (gid < n) o[gid] = a[gid] + b[gid];
}

// ---------------------------------------------------------------------------
extern "C" void kernel_launch(void* const* d_in, const int* in_sizes, int n_in,
                              void* d_out, int out_size)
{
    const float* A     = (const float*)d_in[0];
    const float* Xin   = (const float*)d_in[1];
    const float* W0    = (const float*)d_in[2];
    const float* b0    = (const float*)d_in[3];
    const float* Wb    = (const float*)d_in[4];
    const float* bb    = (const float*)d_in[5];
    const float* We    = (const float*)d_in[6];
    const float* be    = (const float*)d_in[7];
    const float* dW    = (const float*)d_in[8];
    const float* db    = (const float*)d_in[9];
    const float* uW    = (const float*)d_in[10];
    const float* ub    = (const float*)d_in[11];
    const float* pW    = (const float*)d_in[12];
    const float* pwb   = (const float*)d_in[13];
    const float* pb    = (const float*)d_in[14];
    const float* phi   = (const float*)d_in[15];
    const float* agWg  = (const float*)d_in[16];
    const float* agbg  = (const float*)d_in[17];
    const float* agWs  = (const float*)d_in[18];
    const float* agbs  = (const float*)d_in[19];
    const float* agWp  = (const float*)d_in[20];
    const float* agbp  = (const float*)d_in[21];

    float *X0, *X1d, *X2d, *Xb, *X1, *X2, *G, *Xu1, *Xu0, *cat;
    float *h1, *e, *eh, *sc, *vals0, *vals1, *catW, *biasGS;
    int *idx0, *idx1;
    unsigned* bm;
    cudaGetSymbolAddress((void**)&X0,  g_X0);
    cudaGetSymbolAddress((void**)&X1d, g_X1d);
    cudaGetSymbolAddress((void**)&X2d, g_X2d);
    cudaGetSymbolAddress((void**)&Xb,  g_Xb);
    cudaGetSymbolAddress((void**)&X1,  g_X1);
    cudaGetSymbolAddress((void**)&X2,  g_X2);
    cudaGetSymbolAddress((void**)&G,   g_G);
    cudaGetSymbolAddress((void**)&Xu1, g_Xu1);
    cudaGetSymbolAddress((void**)&Xu0, g_Xu0);
    cudaGetSymbolAddress((void**)&cat, g_cat);
    cudaGetSymbolAddress((void**)&bm,  g_bm);
    cudaGetSymbolAddress((void**)&h1,  g_h1);
    cudaGetSymbolAddress((void**)&e,   g_e);
    cudaGetSymbolAddress((void**)&eh,  g_eh);
    cudaGetSymbolAddress((void**)&sc,  g_sc);
    cudaGetSymbolAddress((void**)&vals0, g_vals0);
    cudaGetSymbolAddress((void**)&vals1, g_vals1);
    cudaGetSymbolAddress((void**)&idx0, g_idx0);
    cudaGetSymbolAddress((void**)&idx1, g_idx1);
    cudaGetSymbolAddress((void**)&catW, g_catW);
    cudaGetSymbolAddress((void**)&biasGS, g_biasGS);

    const int WMAT = DD * DD;   // 102400

    auto gemm = [&](int M, int N, int K,
                    const float* Ap, int lda, const float* Bp, int ldb,
                    const float* bias, float* Cp, int ldc,
                    const float* res, int ldres, int act) {
        dim3 grid(N / 64, (M + 63) / 64);
        gemm_tc_kernel<<<grid, 128>>>(M, K, Ap, lda, Bp, ldb, bias, Cp, ldc, res, ldres, act);
    };

    // ---- setup ----
    build_mask_kernel<<<(N0 * N0) / 256, 256>>>(A, bm);
    add_bias_kernel<<<3, 256>>>(agbg, agbs, biasGS, 2 * DD);
    cudaMemcpyAsync(catW,            agWg,        WMAT * 4, cudaMemcpyDeviceToDevice, 0);
    cudaMemcpyAsync(catW + WMAT,     agWs,        WMAT * 4, cudaMemcpyDeviceToDevice, 0);
    cudaMemcpyAsync(catW + 2 * WMAT, agWg + WMAT, WMAT * 4, cudaMemcpyDeviceToDevice, 0);
    cudaMemcpyAsync(catW + 3 * WMAT, agWs + WMAT, WMAT * 4, cudaMemcpyDeviceToDevice, 0);

    // ---- encoder / down path ----
    gemm(N0, DD, DD, Xin, DD, W0, DD, b0, X0, DD, nullptr, 0, 1);
    gemm(N0, DD, DD, X0, DD, dW, DD, db, X1d, DD, nullptr, 0, 1);

    gemv_e_kernel<<<(N0 + 7) / 8, 256>>>(N0, X1d, pW, pwb, pb, phi, h1, e, eh);
    agg0_kernel<<<N0, 128>>>(bm, e, eh, sc);
    rank_select_kernel<<<(N0 + 255) / 256, 256>>>(sc, N0, KK0, idx0, vals0);
    gather_scale_kernel<<<(KK0 * DD + 255) / 256, 256>>>(X1d, idx0, vals0, KK0, X1);

    gemm(KK0, DD, DD, X1, DD, dW + WMAT, DD, db + DD, X2d, DD, nullptr, 0, 1);

    gemv_e_kernel<<<(KK0 + 7) / 8, 256>>>(KK0, X2d, pW + DD, pwb + 1, pb + 1, phi + 2, h1, e, eh);
    agg1_kernel<<<KK0, 256>>>(bm, idx0, KK0, e, eh, sc);
    rank_select_kernel<<<(KK0 + 255) / 256, 256>>>(sc, KK0, KK1, idx1, vals1);
    gather_scale_kernel<<<(KK1 * DD + 255) / 256, 256>>>(X2d, idx1, vals1, KK1, X2);

    gemm(KK1, DD, DD, X2, DD, Wb, DD, bb, Xb, DD, nullptr, 0, 1);

    // ---- up level i=0 (u=1, n=KK0) ----
    zero_kernel<<<(KK0 * DD2 + 255) / 256, 256>>>(cat, KK0 * DD2);
    scatter_kernel<<<(KK1 * DD + 255) / 256, 256>>>(cat, DD2, idx1, Xb, KK1);
    copy_block_kernel<<<(KK0 * DD + 255) / 256, 256>>>(cat + DD, DD2, X2d, DD, KK0);
    gemm(KK0, DD, DD2, cat, DD2, catW, DD, biasGS, G, DD, nullptr, 0, 1);
    gemm(KK0, DD, DD,  G,   DD,  agWp, DD, agbp, cat + DD, DD2, nullptr, 0, 2);
    gemm(KK0, DD, DD2, cat, DD2, uW,   DD, ub,   Xu1, DD, X2d, DD, 1);

    // ---- up level i=1 (u=0, n=N0) ----
    zero_kernel<<<(N0 * DD2 + 255) / 256, 256>>>(cat, N0 * DD2);
    scatter_kernel<<<(KK0 * DD + 255) / 256, 256>>>(cat, DD2, idx0, Xu1, KK0);
    copy_block_kernel<<<(N0 * DD + 255) / 256, 256>>>(cat + DD, DD2, X1d, DD, N0);
    gemm(N0, DD, DD2, cat, DD2, catW + 2 * WMAT, DD, biasGS + DD, G, DD, nullptr, 0, 1);
    gemm(N0, DD, DD,  G,   DD,  agWp + WMAT, DD, agbp + DD, cat + DD, DD2, nullptr, 0, 2);
    gemm(N0, DD, DD2, cat, DD2, uW + 2 * WMAT, DD, ub + DD, Xu0, DD, X1d, DD, 1);

    // ---- head ----
    copy_block_kernel<<<(N0 * DD + 255) / 256, 256>>>(cat,      DD2, Xu0, DD, N0);
    copy_block_kernel<<<(N0 * DD + 255) / 256, 256>>>(cat + DD, DD2, X0,  DD, N0);
    gemm(N0, DD, DD2, cat, DD2, We, DD, be, (float*)d_out, DD, nullptr, 0, 1);

    if (out_size >= 2 * N0 * DD) {
        cudaMemcpyAsync((float*)d_out + (size_t)N0 * DD, X0,
                        (size_t)N0 * DD * sizeof(float), cudaMemcpyDeviceToDevice, 0);
    }
}